// round 15
// baseline (speedup 1.0000x reference)
#include <cuda_runtime.h>

#define NQ 16
#define STATE 65536
#define BATCH 32
#define NL 3
#define ROW (2*STATE + NQ*NQ)   // 131328 floats per output row

#define SMEM_BYTES 65536         // 8192 float2 exchange buffer

// ---------------- device scratch (static: allowed) ----------------
__device__ float g_state[BATCH][STATE];        // 8 MB, L2-resident
__device__ float g_ham[BATCH][640];            // h1[256] | h2[128] | h3[256]

// ---------------- warp reduce (full 32) ----------------
__device__ __forceinline__ float wreduce(float a) {
  a += __shfl_xor_sync(0xffffffffu, a, 16);
  a += __shfl_xor_sync(0xffffffffu, a, 8);
  a += __shfl_xor_sync(0xffffffffu, a, 4);
  a += __shfl_xor_sync(0xffffffffu, a, 2);
  a += __shfl_xor_sync(0xffffffffu, a, 1);
  return a;
}

// ================= packed f32x2 helpers (ptxas won't auto-fuse) =============
__device__ __forceinline__ float2 f2fma(float2 a, float2 b, float2 c) {
  float2 r;
  asm("fma.rn.f32x2 %0, %1, %2, %3;"
      : "=l"(reinterpret_cast<unsigned long long&>(r))
      : "l"(reinterpret_cast<unsigned long long&>(a)),
        "l"(reinterpret_cast<unsigned long long&>(b)),
        "l"(reinterpret_cast<unsigned long long&>(c)));
  return r;
}
__device__ __forceinline__ float2 f2mul(float2 a, float2 b) {
  float2 r;
  asm("mul.rn.f32x2 %0, %1, %2;"
      : "=l"(reinterpret_cast<unsigned long long&>(r))
      : "l"(reinterpret_cast<unsigned long long&>(a)),
        "l"(reinterpret_cast<unsigned long long&>(b)));
  return r;
}
__device__ __forceinline__ float2 bcast2(float x) { return make_float2(x, x); }

__device__ __forceinline__ void cluster_sync() {
  asm volatile("barrier.cluster.arrive.aligned;" ::: "memory");
  asm volatile("barrier.cluster.wait.aligned;"   ::: "memory");
}

// ============ gates on a 32-float2 (64 element) register tile ==============
// tile = pair bit (window LSB, inside float2) + 5 k bits (f2 index)

// rotation on the pair bit: swap trick, fully packed
__device__ __forceinline__ void rot0_p(float2* s, float4 R) {
  const float2 c0 = make_float2(R.x, R.w);   // (r00, r11)
  const float2 c1 = make_float2(R.y, R.z);   // (r01, r10)
  #pragma unroll
  for (int m = 0; m < 32; ++m) {
    float2 v = s[m];
    s[m] = f2fma(c1, make_float2(v.y, v.x), f2mul(c0, v));
  }
}
// rotation on k bit PT (0..4)
template<int PT>
__device__ __forceinline__ void rot_p(float2* s, float4 R) {
  const float2 r00 = bcast2(R.x), r01 = bcast2(R.y);
  const float2 r10 = bcast2(R.z), r11 = bcast2(R.w);
  #pragma unroll
  for (int k = 0; k < 16; ++k) {
    const int i0 = ((k >> PT) << (PT + 1)) | (k & ((1 << PT) - 1));
    const int i1 = i0 | (1 << PT);
    float2 a0 = s[i0], a1 = s[i1];
    s[i0] = f2fma(r01, a1, f2mul(r00, a0));
    s[i1] = f2fma(r11, a1, f2mul(r10, a0));
  }
}
// cnot: control = pair bit, target = k bit 0 (acts on .y halves)
__device__ __forceinline__ void cnot_pair(float2* s, float p) {
  #pragma unroll
  for (int k = 0; k < 16; ++k) {
    float t0 = s[2 * k].y, t1 = s[2 * k + 1].y;
    float d = t1 - t0;
    s[2 * k].y     = fmaf( p, d, t0);
    s[2 * k + 1].y = fmaf(-p, d, t1);
  }
}
// cnot: control = k bit PC, target = k bit PC+1 (fully packed)
template<int PC>
__device__ __forceinline__ void cnot_p(float2* s, float p) {
  const float2 pp = bcast2(p), np = bcast2(-p), neg1 = make_float2(-1.f, -1.f);
  #pragma unroll
  for (int k = 0; k < 8; ++k) {
    const int i0 = ((k >> PC) << (PC + 2)) | (1 << PC) | (k & ((1 << PC) - 1));
    const int i1 = i0 | (1 << (PC + 1));
    float2 t0 = s[i0], t1 = s[i1];
    float2 d = f2fma(t0, neg1, t1);          // t1 - t0
    s[i0] = f2fma(pp, d, t0);
    s[i1] = f2fma(np, d, t1);
  }
}

// XOR swizzle on float2 index: conflict-free for A (stride 32) / B (scalar) views
#define SW(i) ((i) ^ (((i) >> 5) & 15))

// ================= single fused kernel =====================================
// 4 CTAs x 256 thr per batch (cluster 4). Grid 128 -> 1 CTA/SM. Tile 64.
// 3 passes/layer: A(bits 0-5), B(5-10) via SMEM, C(10-15) via L2.
extern "C" __global__ void __cluster_dims__(4, 1, 1) __launch_bounds__(256, 1)
fused_kernel(const float* __restrict__ coords,
             const float* __restrict__ feats,
             const float* __restrict__ rot,
             const float* __restrict__ ent,
             const float* __restrict__ fw1, const float* __restrict__ fb1,
             const float* __restrict__ fw2, const float* __restrict__ fb2,
             const float* __restrict__ hw1, const float* __restrict__ hb1,
             const float* __restrict__ hw2, const float* __restrict__ hb2,
             const float* __restrict__ hw3, const float* __restrict__ hb3,
             float* __restrict__ out) {
  extern __shared__ float2 sm2[];          // 8192 float2 (64KB), XOR-swizzled
  __shared__ float  fin[100];
  __shared__ float  fh1[64];
  __shared__ float  pf[16];
  __shared__ float  hx[64];
  __shared__ float4 rotc[NL][NQ];
  __shared__ float  pcoef[NL][NQ - 1];

  const int cta = blockIdx.x;
  const int b = cta >> 2, r = cta & 3, t = threadIdx.x;
  const int wid = t >> 5, lane = t & 31;
  const int u = (r << 8) | t;              // 0..1023 within batch
  float* st   = g_state[b];
  float* blk  = st + (r << 14);            // CTA's contiguous 16384-elem block
  float* outr = out + (size_t)b * ROW;

  // ================= head: feature MLP (8 warps, ILP) ======================
  if (t < 100) fin[t] = feats[b * 100 + t];
  __syncthreads();
  {
    float acc[8];
    #pragma unroll
    for (int i = 0; i < 8; ++i) {
      const int n = wid + 8 * i;
      const float* w = fw1 + n * 100;
      float a = fin[lane] * w[lane];
      a = fmaf(fin[lane + 32], w[lane + 32], a);
      a = fmaf(fin[lane + 64], w[lane + 64], a);
      if (lane < 4) a = fmaf(fin[lane + 96], w[lane + 96], a);
      acc[i] = a;
    }
    #pragma unroll
    for (int i = 0; i < 8; ++i) acc[i] = wreduce(acc[i]);
    if (lane == 0) {
      #pragma unroll
      for (int i = 0; i < 8; ++i) {
        const int n = wid + 8 * i;
        fh1[n] = fmaxf(acc[i] + fb1[n], 0.f);
      }
    }
  }
  __syncthreads();
  {
    float a0, a1;
    { const float* w = fw2 + wid * 64;
      a0 = fmaf(fh1[lane + 32], w[lane + 32], fh1[lane] * w[lane]); }
    { const float* w = fw2 + (wid + 8) * 64;
      a1 = fmaf(fh1[lane + 32], w[lane + 32], fh1[lane] * w[lane]); }
    a0 = wreduce(a0);
    a1 = wreduce(a1);
    if (lane == 0) { pf[wid] = tanhf(a0 + fb2[wid]); pf[wid + 8] = tanhf(a1 + fb2[wid + 8]); }
  }
  __syncthreads();
  if (t < NL * NQ) {
    int l = t >> 4, q = t & 15;
    float s = pf[q];
    float rx = rot[(l * NQ + q) * 3 + 0] * s * 0.5f;
    float ry = rot[(l * NQ + q) * 3 + 1] * s * 0.5f;
    float rz = rot[(l * NQ + q) * 3 + 2] * s * 0.5f;
    float cx, sx, cy, sy, cz, sz;
    sincosf(rx, &sx, &cx);
    sincosf(ry, &sy, &cy);
    sincosf(rz, &sz, &cz);
    float4 R;
    R.x =  cx * cy * cz;   // R00
    R.y = -sx * sy * sz;   // R01
    R.z =  sx * sy * cz;   // R10
    R.w =  cx * cy * sz;   // R11
    rotc[l][q] = R;
  }
  if (t < NL * (NQ - 1)) {
    int l = t / (NQ - 1), c = t % (NQ - 1);
    pcoef[l][c] = 1.f / (1.f + expf(-ent[l * (NQ - 1) + c]));
  }
  __syncthreads();

  // ================= state simulation (3 passes/layer, tile 64) ============
  float2 s[32];
  #pragma unroll 1
  for (int layer = 0; layer < NL; ++layer) {
    const float4* rb = &rotc[layer][0];
    const float*  pb = &pcoef[layer][0];

    // ---- pass A: tile = elem bits 0-5 (pair = bit 0, k = bits 1-5) ----
    if (layer == 0) {
      #pragma unroll
      for (int m = 0; m < 32; ++m) s[m] = make_float2(0.f, 0.f);
      if (u == 0) s[0].x = 1.f;            // |0...0>
    } else {
      // coalesced copy-in of this CTA's block, then tile read
      const float4* src4 = reinterpret_cast<const float4*>(blk);
      #pragma unroll
      for (int i = 0; i < 16; ++i) {
        float4 v = src4[t + 256 * i];
        int g = 2 * (t + 256 * i);         // f2 idx within block
        sm2[SW(g)]     = make_float2(v.x, v.y);
        sm2[SW(g + 1)] = make_float2(v.z, v.w);
      }
      __syncthreads();
      #pragma unroll
      for (int m = 0; m < 32; ++m) s[m] = sm2[SW((t << 5) | m)];
    }
    // rot 0-5, cnot 0-4
    rot0_p(s, rb[0]);
    rot_p<0>(s, rb[1]); rot_p<1>(s, rb[2]); rot_p<2>(s, rb[3]);
    rot_p<3>(s, rb[4]); rot_p<4>(s, rb[5]);
    cnot_pair(s, pb[0]);
    cnot_p<0>(s, pb[1]); cnot_p<1>(s, pb[2]); cnot_p<2>(s, pb[3]); cnot_p<3>(s, pb[4]);
    // store tile (thread-private slots; no pre-sync needed)
    #pragma unroll
    for (int m = 0; m < 32; ++m) sm2[SW((t << 5) | m)] = s[m];
    __syncthreads();

    // ---- pass B: tile = elem bits 5-10 (pair = bit 5, k = bits 6-10) ----
    {
      const float* smf = reinterpret_cast<const float*>(sm2);
      const int b_hi = (t >> 5) << 10;     // local f2 bits 10-12
      const int b_lo = (t & 31) >> 1;      // local f2 bits 0-3
      const int b_p  = t & 1;              // elem bit 0 (spectator)
      #pragma unroll
      for (int m = 0; m < 32; ++m) {
        const int fa = b_hi | ((2 * m) << 4) | b_lo;
        const int fb = b_hi | ((2 * m + 1) << 4) | b_lo;
        s[m].x = smf[2 * SW(fa) + b_p];
        s[m].y = smf[2 * SW(fb) + b_p];
      }
      // rot 6-10, cnot 5-9
      rot_p<0>(s, rb[6]); rot_p<1>(s, rb[7]); rot_p<2>(s, rb[8]);
      rot_p<3>(s, rb[9]); rot_p<4>(s, rb[10]);
      cnot_pair(s, pb[5]);
      cnot_p<0>(s, pb[6]); cnot_p<1>(s, pb[7]); cnot_p<2>(s, pb[8]); cnot_p<3>(s, pb[9]);
      // store to global in B layout (coalesced: lanes = u low 5)
      const int g_hi = (u >> 5) << 11;
      const int g_lo = u & 31;
      #pragma unroll
      for (int m = 0; m < 32; ++m) {
        st[g_hi | ((2 * m) << 5) | g_lo]     = s[m].x;
        st[g_hi | ((2 * m + 1) << 5) | g_lo] = s[m].y;
      }
    }
    cluster_sync();

    // ---- pass C: tile = elem bits 10-15 (pair = bit 10, k = bits 11-15) ----
    {
      #pragma unroll
      for (int m = 0; m < 32; ++m) {
        s[m].x = st[((2 * m) << 10) | u];  // coalesced (lanes = u low)
        s[m].y = st[((2 * m + 1) << 10) | u];
      }
      // rot 11-15, cnot 10-14
      rot_p<0>(s, rb[11]); rot_p<1>(s, rb[12]); rot_p<2>(s, rb[13]);
      rot_p<3>(s, rb[14]); rot_p<4>(s, rb[15]);
      cnot_pair(s, pb[10]);
      cnot_p<0>(s, pb[11]); cnot_p<1>(s, pb[12]); cnot_p<2>(s, pb[13]); cnot_p<3>(s, pb[14]);
      if (layer == NL - 1) {
        #pragma unroll
        for (int m = 0; m < 32; ++m) {
          const int e0 = ((2 * m) << 10) | u;
          const int e1 = ((2 * m + 1) << 10) | u;
          outr[e0] = s[m].x;         outr[e1] = s[m].y;
          outr[STATE + e0] = 0.f;    outr[STATE + e1] = 0.f;
        }
      } else {
        #pragma unroll
        for (int m = 0; m < 32; ++m) {
          st[((2 * m) << 10) | u]     = s[m].x;
          st[((2 * m + 1) << 10) | u] = s[m].y;
        }
        cluster_sync();
      }
    }
  }

  // ================= tail: Hamiltonian MLP over all 32 warps ===============
  {
    if (t < 60) hx[t] = coords[b * 60 + t];
    __syncthreads();
    const int g8 = lane >> 3, l8 = lane & 7;      // 4 groups of 8 lanes
    const int g16 = lane >> 4, l16 = lane & 15;   // 2 groups of 16 lanes
    float* hm = &g_ham[b][0];

    // ---- h1: 256 neurons, 8 per warp (8-lane groups x 2 iters), in=60 ----
    #pragma unroll
    for (int it = 0; it < 2; ++it) {
      const int n = (r << 6) | (wid << 3) | (it << 2) | g8;
      const float* w = hw1 + n * 60;
      float a = 0.f;
      #pragma unroll
      for (int i = 0; i < 8; ++i) {
        const int k = l8 + 8 * i;
        if (k < 60) a = fmaf(hx[k], w[k], a);
      }
      a += __shfl_xor_sync(0xffffffffu, a, 4);
      a += __shfl_xor_sync(0xffffffffu, a, 2);
      a += __shfl_xor_sync(0xffffffffu, a, 1);
      if (l8 == 0) hm[n] = fmaxf(a + hb1[n], 0.f);
    }
    cluster_sync();

    // ---- h2: 128 neurons, 4 per warp (16-lane groups x 2 iters), in=256 ----
    #pragma unroll
    for (int it = 0; it < 2; ++it) {
      const int n = (r << 5) | (wid << 2) | (it << 1) | g16;
      const float* w = hw2 + n * 256;
      float a = 0.f;
      #pragma unroll
      for (int i = 0; i < 16; ++i) {
        const int k = l16 + 16 * i;
        a = fmaf(hm[k], w[k], a);
      }
      a += __shfl_xor_sync(0xffffffffu, a, 8);
      a += __shfl_xor_sync(0xffffffffu, a, 4);
      a += __shfl_xor_sync(0xffffffffu, a, 2);
      a += __shfl_xor_sync(0xffffffffu, a, 1);
      if (l16 == 0) hm[256 + n] = fmaxf(a + hb2[n], 0.f);
    }
    cluster_sync();

    // ---- h3: 256 neurons, 8 per warp (8-lane groups x 2 iters), in=128 ----
    #pragma unroll
    for (int it = 0; it < 2; ++it) {
      const int n = (r << 6) | (wid << 3) | (it << 2) | g8;
      const float* w = hw3 + n * 128;
      float a = 0.f;
      #pragma unroll
      for (int i = 0; i < 16; ++i) {
        const int k = l8 + 8 * i;
        a = fmaf(hm[256 + k], w[k], a);
      }
      a += __shfl_xor_sync(0xffffffffu, a, 4);
      a += __shfl_xor_sync(0xffffffffu, a, 2);
      a += __shfl_xor_sync(0xffffffffu, a, 1);
      if (l8 == 0) hm[384 + n] = a + hb3[n];
    }
    cluster_sync();

    // ---- output: 256 H entries, 64 per rank ----
    if (t < 64) {
      float mean = 0.f;
      #pragma unroll
      for (int k = 0; k < 60; ++k) mean += hx[k];
      mean *= (1.f / 60.f);
      float v = 0.f;
      #pragma unroll
      for (int k = 0; k < 60; ++k) { float d = hx[k] - mean; v = fmaf(d, d, v); }
      v *= (1.f / 59.f);
      float freq = sqrtf(1.f / (v + 1e-6f)) * 200.f;
      const int idx = (r << 6) | t;
      const int i = idx >> 4, j = idx & 15;
      outr[2 * STATE + idx] =
          0.5f * (hm[384 + idx] + hm[384 + j * 16 + i]) + (i == j ? freq : 0.f);
    }
  }
}

// ---------------- launch ----------------
extern "C" void kernel_launch(void* const* d_in, const int* in_sizes, int n_in,
                              void* d_out, int out_size) {
  const float* coords = (const float*)d_in[0];
  const float* feats  = (const float*)d_in[1];
  const float* rot    = (const float*)d_in[2];
  const float* ent    = (const float*)d_in[3];
  const float* fw1    = (const float*)d_in[4];
  const float* fb1    = (const float*)d_in[5];
  const float* fw2    = (const float*)d_in[6];
  const float* fb2    = (const float*)d_in[7];
  const float* hw1    = (const float*)d_in[8];
  const float* hb1    = (const float*)d_in[9];
  const float* hw2    = (const float*)d_in[10];
  const float* hb2    = (const float*)d_in[11];
  const float* hw3    = (const float*)d_in[12];
  const float* hb3    = (const float*)d_in[13];
  float* out = (float*)d_out;

  cudaFuncSetAttribute(fused_kernel,
                       cudaFuncAttributeMaxDynamicSharedMemorySize, SMEM_BYTES);
  fused_kernel<<<BATCH * 4, 256, SMEM_BYTES>>>(coords, feats, rot, ent,
                                               fw1, fb1, fw2, fb2,
                                               hw1, hb1, hw2, hb2, hw3, hb3, out);
}

// round 16
// speedup vs baseline: 1.1712x; 1.1712x over previous
#include <cuda_runtime.h>

#define NQ 16
#define STATE 65536
#define BATCH 32
#define NL 3
#define ROW (2*STATE + NQ*NQ)   // 131328 floats per output row

#define SMEM_FLOATS 16896        // 16384 elems + skew
#define SMEM_BYTES  (SMEM_FLOATS * 4)

// ---------------- device scratch (static: allowed) ----------------
__device__ float g_state[BATCH][STATE];        // 8 MB, L2-resident

// ---------------- warp reduce (full 32) ----------------
__device__ __forceinline__ float wreduce(float a) {
  a += __shfl_xor_sync(0xffffffffu, a, 16);
  a += __shfl_xor_sync(0xffffffffu, a, 8);
  a += __shfl_xor_sync(0xffffffffu, a, 4);
  a += __shfl_xor_sync(0xffffffffu, a, 2);
  a += __shfl_xor_sync(0xffffffffu, a, 1);
  return a;
}

// ================= packed f32x2 helpers (ptxas won't auto-fuse) =============
__device__ __forceinline__ float2 f2fma(float2 a, float2 b, float2 c) {
  float2 r;
  asm("fma.rn.f32x2 %0, %1, %2, %3;"
      : "=l"(reinterpret_cast<unsigned long long&>(r))
      : "l"(reinterpret_cast<unsigned long long&>(a)),
        "l"(reinterpret_cast<unsigned long long&>(b)),
        "l"(reinterpret_cast<unsigned long long&>(c)));
  return r;
}
__device__ __forceinline__ float2 f2mul(float2 a, float2 b) {
  float2 r;
  asm("mul.rn.f32x2 %0, %1, %2;"
      : "=l"(reinterpret_cast<unsigned long long&>(r))
      : "l"(reinterpret_cast<unsigned long long&>(a)),
        "l"(reinterpret_cast<unsigned long long&>(b)));
  return r;
}
__device__ __forceinline__ float2 bcast2(float x) { return make_float2(x, x); }

__device__ __forceinline__ void cluster_sync() {
  asm volatile("barrier.cluster.arrive.aligned;" ::: "memory");
  asm volatile("barrier.cluster.wait.aligned;"   ::: "memory");
}

// ============ gates on a 16-float2 (32 element) register tile ==============
__device__ __forceinline__ void rot0_p(float2* s, float4 R) {
  const float2 c0 = make_float2(R.x, R.w);   // (r00, r11)
  const float2 c1 = make_float2(R.y, R.z);   // (r01, r10)
  #pragma unroll
  for (int m = 0; m < 16; ++m) {
    float2 v = s[m];
    s[m] = f2fma(c1, make_float2(v.y, v.x), f2mul(c0, v));
  }
}
template<int PT>
__device__ __forceinline__ void rot_p(float2* s, float4 R) {
  const float2 r00 = bcast2(R.x), r01 = bcast2(R.y);
  const float2 r10 = bcast2(R.z), r11 = bcast2(R.w);
  #pragma unroll
  for (int k = 0; k < 8; ++k) {
    const int i0 = ((k >> PT) << (PT + 1)) | (k & ((1 << PT) - 1));
    const int i1 = i0 | (1 << PT);
    float2 a0 = s[i0], a1 = s[i1];
    s[i0] = f2fma(r01, a1, f2mul(r00, a0));
    s[i1] = f2fma(r11, a1, f2mul(r10, a0));
  }
}
template<int PC>
__device__ __forceinline__ void cnot_p(float2* s, float p) {
  const float2 pp = bcast2(p), np = bcast2(-p), neg1 = make_float2(-1.f, -1.f);
  #pragma unroll
  for (int k = 0; k < 4; ++k) {
    const int i0 = ((k >> PC) << (PC + 2)) | (1 << PC) | (k & ((1 << PC) - 1));
    const int i1 = i0 | (1 << (PC + 1));
    float2 t0 = s[i0], t1 = s[i1];
    float2 d = f2fma(t0, neg1, t1);          // t1 - t0
    s[i0] = f2fma(pp, d, t0);
    s[i1] = f2fma(np, d, t1);
  }
}
__device__ __forceinline__ void cnot0_p(float2* s, float p) {
  #pragma unroll
  for (int k = 0; k < 8; ++k) {
    float t0 = s[2 * k].y, t1 = s[2 * k + 1].y;
    float d = t1 - t0;
    s[2 * k].y     = fmaf( p, d, t0);
    s[2 * k + 1].y = fmaf(-p, d, t1);
  }
}

#define SKEW(e) ((e) + ((e) >> 5))   // bank-conflict-free for A/B/C patterns

// ================= single kernel, two CTA roles ============================
// CTAs 0-127: sim (4 CTAs x 512 thr per batch, cluster 4, 1 CTA/SM).
// CTAs 128-159: Hamiltonian MLP (1 CTA per batch) on the 20 spare SMs,
//               fully overlapped with the sim. These clusters never touch
//               the cluster barrier (legal: no CTA of the cluster arrives).
extern "C" __global__ void __cluster_dims__(4, 1, 1) __launch_bounds__(512, 1)
fused_kernel(const float* __restrict__ coords,
             const float* __restrict__ feats,
             const float* __restrict__ rot,
             const float* __restrict__ ent,
             const float* __restrict__ fw1, const float* __restrict__ fb1,
             const float* __restrict__ fw2, const float* __restrict__ fb2,
             const float* __restrict__ hw1, const float* __restrict__ hb1,
             const float* __restrict__ hw2, const float* __restrict__ hb2,
             const float* __restrict__ hw3, const float* __restrict__ hb3,
             float* __restrict__ out) {
  extern __shared__ float sm[];            // 16384 elems + skew (dynamic)
  __shared__ float  fin[100];
  __shared__ float  fh1[64];
  __shared__ float  pf[16];
  __shared__ float4 rotc[NL][NQ];
  __shared__ float  pcoef[NL][NQ - 1];

  const int cta = blockIdx.x;
  const int t = threadIdx.x;
  const int wid = t >> 5, lane = t & 31;

  // ======================= ham role ========================================
  if (cta >= 128) {
    const int hb = cta - 128;              // batch
    float* X  = sm;                        // [64]
    float* H1 = sm + 64;                   // [256]
    float* H2 = sm + 320;                  // [128]
    float* H3 = sm + 448;                  // [256]
    if (t < 60) X[t] = coords[hb * 60 + t];
    __syncthreads();
    // h1: 256 neurons, 16/warp, ILP 4, in=60
    #pragma unroll
    for (int i0 = 0; i0 < 16; i0 += 4) {
      float acc[4];
      #pragma unroll
      for (int j = 0; j < 4; ++j) {
        const int n = wid + 16 * (i0 + j);
        const float* w = hw1 + n * 60;
        float a = X[lane] * w[lane];
        if (lane < 28) a = fmaf(X[lane + 32], w[lane + 32], a);
        acc[j] = a;
      }
      #pragma unroll
      for (int j = 0; j < 4; ++j) acc[j] = wreduce(acc[j]);
      if (lane == 0) {
        #pragma unroll
        for (int j = 0; j < 4; ++j) {
          const int n = wid + 16 * (i0 + j);
          H1[n] = fmaxf(acc[j] + hb1[n], 0.f);
        }
      }
    }
    __syncthreads();
    // h2: 128 neurons, 8/warp, ILP 4, in=256
    #pragma unroll
    for (int i0 = 0; i0 < 8; i0 += 4) {
      float acc[4];
      #pragma unroll
      for (int j = 0; j < 4; ++j) {
        const int n = wid + 16 * (i0 + j);
        const float* w = hw2 + n * 256;
        float a = 0.f;
        #pragma unroll
        for (int k = 0; k < 8; ++k) a = fmaf(H1[lane + 32 * k], w[lane + 32 * k], a);
        acc[j] = a;
      }
      #pragma unroll
      for (int j = 0; j < 4; ++j) acc[j] = wreduce(acc[j]);
      if (lane == 0) {
        #pragma unroll
        for (int j = 0; j < 4; ++j) {
          const int n = wid + 16 * (i0 + j);
          H2[n] = fmaxf(acc[j] + hb2[n], 0.f);
        }
      }
    }
    __syncthreads();
    // h3: 256 neurons, 16/warp, ILP 4, in=128
    #pragma unroll
    for (int i0 = 0; i0 < 16; i0 += 4) {
      float acc[4];
      #pragma unroll
      for (int j = 0; j < 4; ++j) {
        const int n = wid + 16 * (i0 + j);
        const float* w = hw3 + n * 128;
        float a = 0.f;
        #pragma unroll
        for (int k = 0; k < 4; ++k) a = fmaf(H2[lane + 32 * k], w[lane + 32 * k], a);
        acc[j] = a;
      }
      #pragma unroll
      for (int j = 0; j < 4; ++j) acc[j] = wreduce(acc[j]);
      if (lane == 0) {
        #pragma unroll
        for (int j = 0; j < 4; ++j) {
          const int n = wid + 16 * (i0 + j);
          H3[n] = acc[j] + hb3[n];
        }
      }
    }
    __syncthreads();
    // output
    if (t < 256) {
      float mean = 0.f;
      #pragma unroll
      for (int k = 0; k < 60; ++k) mean += X[k];
      mean *= (1.f / 60.f);
      float v = 0.f;
      #pragma unroll
      for (int k = 0; k < 60; ++k) { float d = X[k] - mean; v = fmaf(d, d, v); }
      v *= (1.f / 59.f);
      float freq = sqrtf(1.f / (v + 1e-6f)) * 200.f;
      const int i = t >> 4, j = t & 15;
      out[(size_t)hb * ROW + 2 * STATE + t] =
          0.5f * (H3[t] + H3[j * 16 + i]) + (i == j ? freq : 0.f);
    }
    return;
  }

  // ======================= sim role ========================================
  const int b = cta >> 2, r = cta & 3;
  const int tb = (r << 9) | t;             // 0..2047 within batch
  float* st   = g_state[b];
  float* blk  = st + (r << 14);            // CTA's contiguous 16384-elem block
  float* outr = out + (size_t)b * ROW;

  // ---------------- head: feature MLP (16 warps, ILP) ----------------------
  if (t < 100) fin[t] = feats[b * 100 + t];
  __syncthreads();
  {
    float acc[4];
    #pragma unroll
    for (int i = 0; i < 4; ++i) {
      const int n = wid + 16 * i;
      const float* w = fw1 + n * 100;
      float a = fin[lane] * w[lane];
      a = fmaf(fin[lane + 32], w[lane + 32], a);
      a = fmaf(fin[lane + 64], w[lane + 64], a);
      if (lane < 4) a = fmaf(fin[lane + 96], w[lane + 96], a);
      acc[i] = a;
    }
    #pragma unroll
    for (int i = 0; i < 4; ++i) acc[i] = wreduce(acc[i]);
    if (lane == 0) {
      #pragma unroll
      for (int i = 0; i < 4; ++i) {
        const int n = wid + 16 * i;
        fh1[n] = fmaxf(acc[i] + fb1[n], 0.f);
      }
    }
  }
  __syncthreads();
  {
    const float* w = fw2 + wid * 64;
    float a = fmaf(fh1[lane + 32], w[lane + 32], fh1[lane] * w[lane]);
    a = wreduce(a);
    if (lane == 0) pf[wid] = tanhf(a + fb2[wid]);
  }
  __syncthreads();
  if (t < NL * NQ) {
    int l = t >> 4, q = t & 15;
    float s = pf[q];
    float rx = rot[(l * NQ + q) * 3 + 0] * s * 0.5f;
    float ry = rot[(l * NQ + q) * 3 + 1] * s * 0.5f;
    float rz = rot[(l * NQ + q) * 3 + 2] * s * 0.5f;
    float cx, sx, cy, sy, cz, sz;
    sincosf(rx, &sx, &cx);
    sincosf(ry, &sy, &cy);
    sincosf(rz, &sz, &cz);
    float4 R;
    R.x =  cx * cy * cz;   // R00
    R.y = -sx * sy * sz;   // R01
    R.z =  sx * sy * cz;   // R10
    R.w =  cx * cy * sz;   // R11
    rotc[l][q] = R;
  }
  if (t < NL * (NQ - 1)) {
    int l = t / (NQ - 1), c = t % (NQ - 1);
    pcoef[l][c] = 1.f / (1.f + expf(-ent[l * (NQ - 1) + c]));
  }
  __syncthreads();

  // ---------------- state simulation (verified R14 structure) --------------
  float2 s[16];
  #pragma unroll 1
  for (int layer = 0; layer < NL; ++layer) {
    const float4* rb = &rotc[layer][0];
    const float*  pb = &pcoef[layer][0];

    // ---- load tile for pass A ----
    if (layer == 0) {
      #pragma unroll
      for (int m = 0; m < 16; ++m) s[m] = make_float2(0.f, 0.f);
      if (tb == 0) s[0].x = 1.f;           // |0...0>
    } else {
      const float4* src4 = reinterpret_cast<const float4*>(blk);
      #pragma unroll
      for (int i = t; i < 4096; i += 512) {
        float4 v = src4[i];
        int p = SKEW(4 * i);
        sm[p] = v.x; sm[p + 1] = v.y; sm[p + 2] = v.z; sm[p + 3] = v.w;
      }
      __syncthreads();
      #pragma unroll
      for (int m = 0; m < 16; ++m) {
        int p = SKEW(t * 32 + 2 * m);
        s[m].x = sm[p]; s[m].y = sm[p + 1];
      }
    }

    // ---- pass A: rot 0-4, cnot 0-3 (tile slots are thread-private) ----
    rot0_p(s, rb[0]);
    rot_p<0>(s, rb[1]); rot_p<1>(s, rb[2]); rot_p<2>(s, rb[3]); rot_p<3>(s, rb[4]);
    cnot0_p(s, pb[0]);
    cnot_p<0>(s, pb[1]); cnot_p<1>(s, pb[2]); cnot_p<2>(s, pb[3]);
    #pragma unroll
    for (int m = 0; m < 16; ++m) {
      int p = SKEW(t * 32 + 2 * m);
      sm[p] = s[m].x; sm[p + 1] = s[m].y;
    }
    __syncthreads();

    // ---- pass B: rot 5-8, cnot 4-7 (slots thread-private: no mid sync) ----
    {
      const int eb = ((t >> 4) << 9) | (t & 15);
      #pragma unroll
      for (int m = 0; m < 16; ++m) {
        s[m].x = sm[SKEW(eb | ((2 * m) << 4))];
        s[m].y = sm[SKEW(eb | ((2 * m + 1) << 4))];
      }
      rot_p<0>(s, rb[5]); rot_p<1>(s, rb[6]); rot_p<2>(s, rb[7]); rot_p<3>(s, rb[8]);
      cnot0_p(s, pb[4]);
      cnot_p<0>(s, pb[5]); cnot_p<1>(s, pb[6]); cnot_p<2>(s, pb[7]);
      #pragma unroll
      for (int m = 0; m < 16; ++m) {
        sm[SKEW(eb | ((2 * m) << 4))]     = s[m].x;
        sm[SKEW(eb | ((2 * m + 1) << 4))] = s[m].y;
      }
    }
    __syncthreads();

    // ---- pass C: rot 9-12, cnot 8-11 (window bits 8-12); write global ----
    {
      const int ec = ((t >> 8) << 13) | (t & 255);
      #pragma unroll
      for (int m = 0; m < 16; ++m) {
        s[m].x = sm[SKEW(ec | ((2 * m) << 8))];
        s[m].y = sm[SKEW(ec | ((2 * m + 1) << 8))];
      }
      rot_p<0>(s, rb[9]); rot_p<1>(s, rb[10]); rot_p<2>(s, rb[11]); rot_p<3>(s, rb[12]);
      cnot0_p(s, pb[8]);
      cnot_p<0>(s, pb[9]); cnot_p<1>(s, pb[10]); cnot_p<2>(s, pb[11]);
      #pragma unroll
      for (int m = 0; m < 16; ++m) {
        blk[ec | ((2 * m) << 8)]     = s[m].x;   // coalesced (lanes = t low)
        blk[ec | ((2 * m + 1) << 8)] = s[m].y;
      }
    }
    cluster_sync();

    // ---- pass D: rot 13-15, cnot 12-14 (window bits 11-15); global r/w ----
    {
      #pragma unroll
      for (int m = 0; m < 16; ++m) {
        s[m].x = st[((2 * m) << 11) | tb];
        s[m].y = st[((2 * m + 1) << 11) | tb];
      }
      rot_p<1>(s, rb[13]); rot_p<2>(s, rb[14]); rot_p<3>(s, rb[15]);
      cnot_p<0>(s, pb[12]); cnot_p<1>(s, pb[13]); cnot_p<2>(s, pb[14]);
      if (layer == NL - 1) {
        #pragma unroll
        for (int m = 0; m < 16; ++m) {
          int e0 = ((2 * m) << 11) | tb;
          int e1 = ((2 * m + 1) << 11) | tb;
          outr[e0] = s[m].x;         outr[e1] = s[m].y;
          outr[STATE + e0] = 0.f;    outr[STATE + e1] = 0.f;
        }
      } else {
        #pragma unroll
        for (int m = 0; m < 16; ++m) {
          st[((2 * m) << 11) | tb]     = s[m].x;
          st[((2 * m + 1) << 11) | tb] = s[m].y;
        }
        cluster_sync();
      }
    }
  }
}

// ---------------- launch ----------------
extern "C" void kernel_launch(void* const* d_in, const int* in_sizes, int n_in,
                              void* d_out, int out_size) {
  const float* coords = (const float*)d_in[0];
  const float* feats  = (const float*)d_in[1];
  const float* rot    = (const float*)d_in[2];
  const float* ent    = (const float*)d_in[3];
  const float* fw1    = (const float*)d_in[4];
  const float* fb1    = (const float*)d_in[5];
  const float* fw2    = (const float*)d_in[6];
  const float* fb2    = (const float*)d_in[7];
  const float* hw1    = (const float*)d_in[8];
  const float* hb1    = (const float*)d_in[9];
  const float* hw2    = (const float*)d_in[10];
  const float* hb2    = (const float*)d_in[11];
  const float* hw3    = (const float*)d_in[12];
  const float* hb3    = (const float*)d_in[13];
  float* out = (float*)d_out;

  cudaFuncSetAttribute(fused_kernel,
                       cudaFuncAttributeMaxDynamicSharedMemorySize, SMEM_BYTES);
  fused_kernel<<<BATCH * 4 + BATCH, 512, SMEM_BYTES>>>(coords, feats, rot, ent,
                                                       fw1, fb1, fw2, fb2,
                                                       hw1, hb1, hw2, hb2,
                                                       hw3, hb3, out);
}

// round 17
// speedup vs baseline: 1.5379x; 1.3131x over previous
#include <cuda_runtime.h>

#define NQ 16
#define STATE 65536
#define BATCH 32
#define NL 3
#define ROW (2*STATE + NQ*NQ)   // 131328 floats per output row

#define SMEM_FLOATS 16896        // 16384 elems + skew
#define SMEM_BYTES  (SMEM_FLOATS * 4)

// ---------------- device scratch (static: allowed) ----------------
__device__ float g_state[BATCH][STATE];        // 8 MB, L2-resident

// ---------------- warp reduce (full 32) ----------------
__device__ __forceinline__ float wreduce(float a) {
  a += __shfl_xor_sync(0xffffffffu, a, 16);
  a += __shfl_xor_sync(0xffffffffu, a, 8);
  a += __shfl_xor_sync(0xffffffffu, a, 4);
  a += __shfl_xor_sync(0xffffffffu, a, 2);
  a += __shfl_xor_sync(0xffffffffu, a, 1);
  return a;
}

// ================= packed f32x2 helpers (ptxas won't auto-fuse) =============
__device__ __forceinline__ float2 f2fma(float2 a, float2 b, float2 c) {
  float2 r;
  asm("fma.rn.f32x2 %0, %1, %2, %3;"
      : "=l"(reinterpret_cast<unsigned long long&>(r))
      : "l"(reinterpret_cast<unsigned long long&>(a)),
        "l"(reinterpret_cast<unsigned long long&>(b)),
        "l"(reinterpret_cast<unsigned long long&>(c)));
  return r;
}
__device__ __forceinline__ float2 f2mul(float2 a, float2 b) {
  float2 r;
  asm("mul.rn.f32x2 %0, %1, %2;"
      : "=l"(reinterpret_cast<unsigned long long&>(r))
      : "l"(reinterpret_cast<unsigned long long&>(a)),
        "l"(reinterpret_cast<unsigned long long&>(b)));
  return r;
}
__device__ __forceinline__ float2 bcast2(float x) { return make_float2(x, x); }

__device__ __forceinline__ void cluster_sync() {
  asm volatile("barrier.cluster.arrive.aligned;" ::: "memory");
  asm volatile("barrier.cluster.wait.aligned;"   ::: "memory");
}

// ============ gates on a 16-float2 (32 element) register tile ==============
__device__ __forceinline__ void rot0_p(float2* s, float4 R) {
  const float2 c0 = make_float2(R.x, R.w);   // (r00, r11)
  const float2 c1 = make_float2(R.y, R.z);   // (r01, r10)
  #pragma unroll
  for (int m = 0; m < 16; ++m) {
    float2 v = s[m];
    s[m] = f2fma(c1, make_float2(v.y, v.x), f2mul(c0, v));
  }
}
template<int PT>
__device__ __forceinline__ void rot_p(float2* s, float4 R) {
  const float2 r00 = bcast2(R.x), r01 = bcast2(R.y);
  const float2 r10 = bcast2(R.z), r11 = bcast2(R.w);
  #pragma unroll
  for (int k = 0; k < 8; ++k) {
    const int i0 = ((k >> PT) << (PT + 1)) | (k & ((1 << PT) - 1));
    const int i1 = i0 | (1 << PT);
    float2 a0 = s[i0], a1 = s[i1];
    s[i0] = f2fma(r01, a1, f2mul(r00, a0));
    s[i1] = f2fma(r11, a1, f2mul(r10, a0));
  }
}
template<int PC>
__device__ __forceinline__ void cnot_p(float2* s, float p) {
  const float2 pp = bcast2(p), np = bcast2(-p), neg1 = make_float2(-1.f, -1.f);
  #pragma unroll
  for (int k = 0; k < 4; ++k) {
    const int i0 = ((k >> PC) << (PC + 2)) | (1 << PC) | (k & ((1 << PC) - 1));
    const int i1 = i0 | (1 << (PC + 1));
    float2 t0 = s[i0], t1 = s[i1];
    float2 d = f2fma(t0, neg1, t1);          // t1 - t0
    s[i0] = f2fma(pp, d, t0);
    s[i1] = f2fma(np, d, t1);
  }
}
__device__ __forceinline__ void cnot0_p(float2* s, float p) {
  #pragma unroll
  for (int k = 0; k < 8; ++k) {
    float t0 = s[2 * k].y, t1 = s[2 * k + 1].y;
    float d = t1 - t0;
    s[2 * k].y     = fmaf( p, d, t0);
    s[2 * k + 1].y = fmaf(-p, d, t1);
  }
}

#define SKEW(e) ((e) + ((e) >> 5))   // bank-conflict-free for A/B/C patterns

// ================= single kernel, two CTA roles ============================
// CTAs 0-127: sim (4 CTAs x 512 thr per batch, cluster 4, 1 CTA/SM).
//   Layer 0 is evaluated EXACTLY as a scalar chain product (|0..0> input:
//   rotations give a product state; the ascending CNOT chain makes each
//   factor depend only on the previous bit). Layers 1-2 use the verified
//   4-pass window structure.
// CTAs 128-159: Hamiltonian MLP (1 CTA per batch), overlapped with the sim.
extern "C" __global__ void __cluster_dims__(4, 1, 1) __launch_bounds__(512, 1)
fused_kernel(const float* __restrict__ coords,
             const float* __restrict__ feats,
             const float* __restrict__ rot,
             const float* __restrict__ ent,
             const float* __restrict__ fw1, const float* __restrict__ fb1,
             const float* __restrict__ fw2, const float* __restrict__ fb2,
             const float* __restrict__ hw1, const float* __restrict__ hb1,
             const float* __restrict__ hw2, const float* __restrict__ hb2,
             const float* __restrict__ hw3, const float* __restrict__ hb3,
             float* __restrict__ out) {
  extern __shared__ float sm[];            // 16384 elems + skew (dynamic)
  __shared__ float  fin[100];
  __shared__ float  fh1[64];
  __shared__ float  pf[16];
  __shared__ float4 rotc[NL][NQ];
  __shared__ float  pcoef[NL][NQ - 1];
  __shared__ float  g0c[2];                // chain factor q=0
  __shared__ float  gq[16][2][2];          // chain factors q=1..15: [q][c][x]

  const int cta = blockIdx.x;
  const int t = threadIdx.x;
  const int wid = t >> 5, lane = t & 31;

  // ======================= ham role ========================================
  if (cta >= 128) {
    const int hb = cta - 128;              // batch
    float* X  = sm;                        // [64]
    float* H1 = sm + 64;                   // [256]
    float* H2 = sm + 320;                  // [128]
    float* H3 = sm + 448;                  // [256]
    if (t < 60) X[t] = coords[hb * 60 + t];
    __syncthreads();
    // h1: 256 neurons, 16/warp, ILP 4, in=60
    #pragma unroll
    for (int i0 = 0; i0 < 16; i0 += 4) {
      float acc[4];
      #pragma unroll
      for (int j = 0; j < 4; ++j) {
        const int n = wid + 16 * (i0 + j);
        const float* w = hw1 + n * 60;
        float a = X[lane] * w[lane];
        if (lane < 28) a = fmaf(X[lane + 32], w[lane + 32], a);
        acc[j] = a;
      }
      #pragma unroll
      for (int j = 0; j < 4; ++j) acc[j] = wreduce(acc[j]);
      if (lane == 0) {
        #pragma unroll
        for (int j = 0; j < 4; ++j) {
          const int n = wid + 16 * (i0 + j);
          H1[n] = fmaxf(acc[j] + hb1[n], 0.f);
        }
      }
    }
    __syncthreads();
    // h2: 128 neurons, 8/warp, ILP 4, in=256
    #pragma unroll
    for (int i0 = 0; i0 < 8; i0 += 4) {
      float acc[4];
      #pragma unroll
      for (int j = 0; j < 4; ++j) {
        const int n = wid + 16 * (i0 + j);
        const float* w = hw2 + n * 256;
        float a = 0.f;
        #pragma unroll
        for (int k = 0; k < 8; ++k) a = fmaf(H1[lane + 32 * k], w[lane + 32 * k], a);
        acc[j] = a;
      }
      #pragma unroll
      for (int j = 0; j < 4; ++j) acc[j] = wreduce(acc[j]);
      if (lane == 0) {
        #pragma unroll
        for (int j = 0; j < 4; ++j) {
          const int n = wid + 16 * (i0 + j);
          H2[n] = fmaxf(acc[j] + hb2[n], 0.f);
        }
      }
    }
    __syncthreads();
    // h3: 256 neurons, 16/warp, ILP 4, in=128
    #pragma unroll
    for (int i0 = 0; i0 < 16; i0 += 4) {
      float acc[4];
      #pragma unroll
      for (int j = 0; j < 4; ++j) {
        const int n = wid + 16 * (i0 + j);
        const float* w = hw3 + n * 128;
        float a = 0.f;
        #pragma unroll
        for (int k = 0; k < 4; ++k) a = fmaf(H2[lane + 32 * k], w[lane + 32 * k], a);
        acc[j] = a;
      }
      #pragma unroll
      for (int j = 0; j < 4; ++j) acc[j] = wreduce(acc[j]);
      if (lane == 0) {
        #pragma unroll
        for (int j = 0; j < 4; ++j) {
          const int n = wid + 16 * (i0 + j);
          H3[n] = acc[j] + hb3[n];
        }
      }
    }
    __syncthreads();
    // output
    if (t < 256) {
      float mean = 0.f;
      #pragma unroll
      for (int k = 0; k < 60; ++k) mean += X[k];
      mean *= (1.f / 60.f);
      float v = 0.f;
      #pragma unroll
      for (int k = 0; k < 60; ++k) { float d = X[k] - mean; v = fmaf(d, d, v); }
      v *= (1.f / 59.f);
      float freq = sqrtf(1.f / (v + 1e-6f)) * 200.f;
      const int i = t >> 4, j = t & 15;
      out[(size_t)hb * ROW + 2 * STATE + t] =
          0.5f * (H3[t] + H3[j * 16 + i]) + (i == j ? freq : 0.f);
    }
    return;
  }

  // ======================= sim role ========================================
  const int b = cta >> 2, r = cta & 3;
  const int tb = (r << 9) | t;             // 0..2047 within batch
  float* st   = g_state[b];
  float* blk  = st + (r << 14);            // CTA's contiguous 16384-elem block
  float* outr = out + (size_t)b * ROW;

  // ---------------- head: feature MLP (16 warps, ILP) ----------------------
  if (t < 100) fin[t] = feats[b * 100 + t];
  __syncthreads();
  {
    float acc[4];
    #pragma unroll
    for (int i = 0; i < 4; ++i) {
      const int n = wid + 16 * i;
      const float* w = fw1 + n * 100;
      float a = fin[lane] * w[lane];
      a = fmaf(fin[lane + 32], w[lane + 32], a);
      a = fmaf(fin[lane + 64], w[lane + 64], a);
      if (lane < 4) a = fmaf(fin[lane + 96], w[lane + 96], a);
      acc[i] = a;
    }
    #pragma unroll
    for (int i = 0; i < 4; ++i) acc[i] = wreduce(acc[i]);
    if (lane == 0) {
      #pragma unroll
      for (int i = 0; i < 4; ++i) {
        const int n = wid + 16 * i;
        fh1[n] = fmaxf(acc[i] + fb1[n], 0.f);
      }
    }
  }
  __syncthreads();
  {
    const float* w = fw2 + wid * 64;
    float a = fmaf(fh1[lane + 32], w[lane + 32], fh1[lane] * w[lane]);
    a = wreduce(a);
    if (lane == 0) pf[wid] = tanhf(a + fb2[wid]);
  }
  __syncthreads();
  if (t < NL * NQ) {
    int l = t >> 4, q = t & 15;
    float s = pf[q];
    float rx = rot[(l * NQ + q) * 3 + 0] * s * 0.5f;
    float ry = rot[(l * NQ + q) * 3 + 1] * s * 0.5f;
    float rz = rot[(l * NQ + q) * 3 + 2] * s * 0.5f;
    float cx, sx, cy, sy, cz, sz;
    sincosf(rx, &sx, &cx);
    sincosf(ry, &sy, &cy);
    sincosf(rz, &sz, &cz);
    float4 R;
    R.x =  cx * cy * cz;   // R00
    R.y = -sx * sy * sz;   // R01
    R.z =  sx * sy * cz;   // R10
    R.w =  cx * cy * sz;   // R11
    rotc[l][q] = R;
  }
  if (t < NL * (NQ - 1)) {
    int l = t / (NQ - 1), c = t % (NQ - 1);
    pcoef[l][c] = 1.f / (1.f + expf(-ent[l * (NQ - 1) + c]));
  }
  __syncthreads();

  // ---------------- layer-0 chain tables -----------------------------------
  // g0c[x0] = r_0(x0); gq[q][c][x] = c==0 ? r_q(x)
  //                                 : (1-p_{q-1}) r_q(x) + p_{q-1} r_q(1-x)
  if (t < 64) {
    const int q = t >> 2, c = (t >> 1) & 1, x = t & 1;
    const float rv0 = rotc[0][q].x, rv1 = rotc[0][q].z;   // column 0 of R
    const float vx = x ? rv1 : rv0, vo = x ? rv0 : rv1;
    if (q == 0) { if (c == 0) g0c[x] = vx; }
    else {
      const float p = pcoef[0][q - 1];
      gq[q][c][x] = c ? fmaf(p, vo - vx, vx) : vx;
    }
  }
  __syncthreads();

  // ---------------- layer 0: exact chain-product evaluation ----------------
  // elem e = (r<<14) | (t<<5) | idx.  amp(e) = g0c[x0] * prod gq[q][x_{q-1}][x_q]
  float2 s[16];
  {
    const int hi = (r << 14) | (t << 5);   // bits 5..15
    float T = 1.f;
    #pragma unroll
    for (int q = 6; q <= 15; ++q)
      T *= gq[q][(hi >> (q - 1)) & 1][(hi >> q) & 1];
    const int x5 = (hi >> 5) & 1;
    const float S0 = gq[5][0][x5] * T;
    const float S1 = gq[5][1][x5] * T;
    float P2[4], P3[8], P4[16];
    #pragma unroll
    for (int i = 0; i < 4; ++i)  P2[i] = g0c[i & 1] * gq[1][i & 1][(i >> 1) & 1];
    #pragma unroll
    for (int i = 0; i < 8; ++i)  P3[i] = P2[i & 3] * gq[2][(i >> 1) & 1][(i >> 2) & 1];
    #pragma unroll
    for (int i = 0; i < 16; ++i) P4[i] = P3[i & 7] * gq[3][(i >> 2) & 1][(i >> 3) & 1];
    float m4[4];                           // gq[4][x3][x4] * S(x4)
    #pragma unroll
    for (int j = 0; j < 4; ++j)
      m4[j] = gq[4][j & 1][(j >> 1) & 1] * ((j >> 1) ? S1 : S0);
    #pragma unroll
    for (int m = 0; m < 16; ++m) {
      const int i0 = 2 * m, i1 = 2 * m + 1;
      s[m].x = P4[i0 & 15] * m4[((i0 >> 3) & 1) | (((i0 >> 4) & 1) << 1)];
      s[m].y = P4[i1 & 15] * m4[((i1 >> 3) & 1) | (((i1 >> 4) & 1) << 1)];
    }
  }

  // ---------------- layers 1..2: verified 4-pass structure -----------------
  #pragma unroll 1
  for (int layer = 1; layer < NL; ++layer) {
    const float4* rb = &rotc[layer][0];
    const float*  pb = &pcoef[layer][0];

    // ---- load tile for pass A (layer 1 already has it from the chain) ----
    if (layer != 1) {
      const float4* src4 = reinterpret_cast<const float4*>(blk);
      #pragma unroll
      for (int i = t; i < 4096; i += 512) {
        float4 v = src4[i];
        int p = SKEW(4 * i);
        sm[p] = v.x; sm[p + 1] = v.y; sm[p + 2] = v.z; sm[p + 3] = v.w;
      }
      __syncthreads();
      #pragma unroll
      for (int m = 0; m < 16; ++m) {
        int p = SKEW(t * 32 + 2 * m);
        s[m].x = sm[p]; s[m].y = sm[p + 1];
      }
    }

    // ---- pass A: rot 0-4, cnot 0-3 (tile slots are thread-private) ----
    rot0_p(s, rb[0]);
    rot_p<0>(s, rb[1]); rot_p<1>(s, rb[2]); rot_p<2>(s, rb[3]); rot_p<3>(s, rb[4]);
    cnot0_p(s, pb[0]);
    cnot_p<0>(s, pb[1]); cnot_p<1>(s, pb[2]); cnot_p<2>(s, pb[3]);
    #pragma unroll
    for (int m = 0; m < 16; ++m) {
      int p = SKEW(t * 32 + 2 * m);
      sm[p] = s[m].x; sm[p + 1] = s[m].y;
    }
    __syncthreads();

    // ---- pass B: rot 5-8, cnot 4-7 (slots thread-private: no mid sync) ----
    {
      const int eb = ((t >> 4) << 9) | (t & 15);
      #pragma unroll
      for (int m = 0; m < 16; ++m) {
        s[m].x = sm[SKEW(eb | ((2 * m) << 4))];
        s[m].y = sm[SKEW(eb | ((2 * m + 1) << 4))];
      }
      rot_p<0>(s, rb[5]); rot_p<1>(s, rb[6]); rot_p<2>(s, rb[7]); rot_p<3>(s, rb[8]);
      cnot0_p(s, pb[4]);
      cnot_p<0>(s, pb[5]); cnot_p<1>(s, pb[6]); cnot_p<2>(s, pb[7]);
      #pragma unroll
      for (int m = 0; m < 16; ++m) {
        sm[SKEW(eb | ((2 * m) << 4))]     = s[m].x;
        sm[SKEW(eb | ((2 * m + 1) << 4))] = s[m].y;
      }
    }
    __syncthreads();

    // ---- pass C: rot 9-12, cnot 8-11 (window bits 8-12); write global ----
    {
      const int ec = ((t >> 8) << 13) | (t & 255);
      #pragma unroll
      for (int m = 0; m < 16; ++m) {
        s[m].x = sm[SKEW(ec | ((2 * m) << 8))];
        s[m].y = sm[SKEW(ec | ((2 * m + 1) << 8))];
      }
      rot_p<0>(s, rb[9]); rot_p<1>(s, rb[10]); rot_p<2>(s, rb[11]); rot_p<3>(s, rb[12]);
      cnot0_p(s, pb[8]);
      cnot_p<0>(s, pb[9]); cnot_p<1>(s, pb[10]); cnot_p<2>(s, pb[11]);
      #pragma unroll
      for (int m = 0; m < 16; ++m) {
        blk[ec | ((2 * m) << 8)]     = s[m].x;   // coalesced (lanes = t low)
        blk[ec | ((2 * m + 1) << 8)] = s[m].y;
      }
    }
    cluster_sync();

    // ---- pass D: rot 13-15, cnot 12-14 (window bits 11-15); global r/w ----
    {
      #pragma unroll
      for (int m = 0; m < 16; ++m) {
        s[m].x = st[((2 * m) << 11) | tb];
        s[m].y = st[((2 * m + 1) << 11) | tb];
      }
      rot_p<1>(s, rb[13]); rot_p<2>(s, rb[14]); rot_p<3>(s, rb[15]);
      cnot_p<0>(s, pb[12]); cnot_p<1>(s, pb[13]); cnot_p<2>(s, pb[14]);
      if (layer == NL - 1) {
        #pragma unroll
        for (int m = 0; m < 16; ++m) {
          int e0 = ((2 * m) << 11) | tb;
          int e1 = ((2 * m + 1) << 11) | tb;
          outr[e0] = s[m].x;         outr[e1] = s[m].y;
          outr[STATE + e0] = 0.f;    outr[STATE + e1] = 0.f;
        }
      } else {
        #pragma unroll
        for (int m = 0; m < 16; ++m) {
          st[((2 * m) << 11) | tb]     = s[m].x;
          st[((2 * m + 1) << 11) | tb] = s[m].y;
        }
        cluster_sync();
      }
    }
  }
}

// ---------------- launch ----------------
extern "C" void kernel_launch(void* const* d_in, const int* in_sizes, int n_in,
                              void* d_out, int out_size) {
  const float* coords = (const float*)d_in[0];
  const float* feats  = (const float*)d_in[1];
  const float* rot    = (const float*)d_in[2];
  const float* ent    = (const float*)d_in[3];
  const float* fw1    = (const float*)d_in[4];
  const float* fb1    = (const float*)d_in[5];
  const float* fw2    = (const float*)d_in[6];
  const float* fb2    = (const float*)d_in[7];
  const float* hw1    = (const float*)d_in[8];
  const float* hb1    = (const float*)d_in[9];
  const float* hw2    = (const float*)d_in[10];
  const float* hb2    = (const float*)d_in[11];
  const float* hw3    = (const float*)d_in[12];
  const float* hb3    = (const float*)d_in[13];
  float* out = (float*)d_out;

  cudaFuncSetAttribute(fused_kernel,
                       cudaFuncAttributeMaxDynamicSharedMemorySize, SMEM_BYTES);
  fused_kernel<<<BATCH * 4 + BATCH, 512, SMEM_BYTES>>>(coords, feats, rot, ent,
                                                       fw1, fb1, fw2, fb2,
                                                       hw1, hb1, hw2, hb2,
                                                       hw3, hb3, out);
}